// round 10
// baseline (speedup 1.0000x reference)
#include <cuda_runtime.h>

// NeuS volume-rendering weights, telescoped closed form. 2 rays per warp,
// all 10 global loads front-batched for doubled memory-level parallelism.
//
//   sig = sigmoid(sdf * s)
//   trans[i] = sig[i]/sig[0]  (telescoping cumprod), trans[0] := 0
//   weight[i] = max(0, sig[i]-sig[i+1]) / sig[0],  1 <= i <= S-2
//   weight[0] = weight[S-1] = 0
//   pixel = sum w*(c - bg) + bg   (background folded; no wsum reduction)
//
// Outputs concatenated into d_out:
//   pixel [R,3] @0, invdepth [R] @R*3, weight [R,S] @R*4

#define N_RAYS    65536
#define N_SAMPLES 128
#define WARPS_PER_BLOCK 8
#define RPW 2   // rays per warp

__device__ __forceinline__ void process_ray(
    unsigned ray, unsigned lane,
    const float4 sd, const float4 z, const float4* __restrict__ wb,
    float s, float bgr, float bgg, float bgb,
    float* __restrict__ out)
{
    // sigmoid via MUFU exp + fast division
    const float sg0 = __fdividef(1.0f, 1.0f + __expf(-sd.x * s));
    const float sg1 = __fdividef(1.0f, 1.0f + __expf(-sd.y * s));
    const float sg2 = __fdividef(1.0f, 1.0f + __expf(-sd.z * s));
    const float sg3 = __fdividef(1.0f, 1.0f + __expf(-sd.w * s));

    const float nxt  = __shfl_down_sync(0xffffffffu, sg0, 1);
    const float sig0 = __shfl_sync(0xffffffffu, sg0, 0);
    const float inv0 = __fdividef(1.0f, sig0);

    float w0 = fmaxf(sg0 - sg1, 0.0f) * inv0;
    float w1 = fmaxf(sg1 - sg2, 0.0f) * inv0;
    float w2 = fmaxf(sg2 - sg3, 0.0f) * inv0;
    float w3 = (lane == 31u) ? 0.0f : fmaxf(sg3 - nxt, 0.0f) * inv0;
    if (lane == 0u) w0 = 0.0f;   // trans[0] = 0

    // streaming store of weights [R,S]
    float* out_weight = out + (size_t)N_RAYS * 4;
    __stcs(reinterpret_cast<float4*>(out_weight + (size_t)ray * N_SAMPLES) + lane,
           make_float4(w0, w1, w2, w3));

    // invdepth
    float invd = w0 * __fdividef(1.0f, z.x)
               + w1 * __fdividef(1.0f, z.y)
               + w2 * __fdividef(1.0f, z.z)
               + w3 * __fdividef(1.0f, z.w);

    // this lane's 4 samples of color from smem (conflict-free LDS.128)
    const float4 c0 = wb[lane * 3 + 0];
    const float4 c1 = wb[lane * 3 + 1];
    const float4 c2 = wb[lane * 3 + 2];

    float r = w0 * (c0.x - bgr) + w1 * (c0.w - bgr)
            + w2 * (c1.z - bgr) + w3 * (c2.y - bgr);
    float g = w0 * (c0.y - bgg) + w1 * (c1.x - bgg)
            + w2 * (c1.w - bgg) + w3 * (c2.z - bgg);
    float b = w0 * (c0.z - bgb) + w1 * (c1.y - bgb)
            + w2 * (c2.x - bgb) + w3 * (c2.w - bgb);

    // warp butterfly reduction of 4 values
    #pragma unroll
    for (int off = 16; off > 0; off >>= 1) {
        r    += __shfl_xor_sync(0xffffffffu, r,    off);
        g    += __shfl_xor_sync(0xffffffffu, g,    off);
        b    += __shfl_xor_sync(0xffffffffu, b,    off);
        invd += __shfl_xor_sync(0xffffffffu, invd, off);
    }

    if (lane == 0u) {
        out[ray * 3 + 0] = r + bgr;
        out[ray * 3 + 1] = g + bgg;
        out[ray * 3 + 2] = b + bgb;
        out[(size_t)N_RAYS * 3 + ray] = invd;
    }
}

__global__ void __launch_bounds__(256)
neus_render_kernel(const float* __restrict__ sdf,
                   const float* __restrict__ color,
                   const float* __restrict__ z_vals,
                   const float* __restrict__ s_ptr,
                   const float* __restrict__ bg_color,
                   float* __restrict__ out)
{
    // per-warp color staging: 2 rays x 96 float4  (24 KB/block)
    __shared__ float4 cbuf[WARPS_PER_BLOCK * RPW * 96];

    const unsigned wid  = threadIdx.x >> 5;
    const unsigned lane = threadIdx.x & 31u;
    const unsigned gw   = blockIdx.x * WARPS_PER_BLOCK + wid;
    const unsigned ray0 = gw * RPW;
    const unsigned ray1 = ray0 + 1;

    // ---- front-batch ALL 10 global loads (max MLP) ----
    const float4* cgA = reinterpret_cast<const float4*>(
                            color + (size_t)ray0 * N_SAMPLES * 3);
    const float4* cgB = reinterpret_cast<const float4*>(
                            color + (size_t)ray1 * N_SAMPLES * 3);
    const float4 a0 = cgA[lane];
    const float4 a1 = cgA[lane + 32];
    const float4 a2 = cgA[lane + 64];
    const float4 b0 = cgB[lane];
    const float4 b1 = cgB[lane + 32];
    const float4 b2 = cgB[lane + 64];
    const float4 sdA = reinterpret_cast<const float4*>(
                           sdf + (size_t)ray0 * N_SAMPLES)[lane];
    const float4 sdB = reinterpret_cast<const float4*>(
                           sdf + (size_t)ray1 * N_SAMPLES)[lane];
    const float4 zA  = reinterpret_cast<const float4*>(
                           z_vals + (size_t)ray0 * N_SAMPLES)[lane];
    const float4 zB  = reinterpret_cast<const float4*>(
                           z_vals + (size_t)ray1 * N_SAMPLES)[lane];

    // stage both rays' color rows through smem (coalesced GMEM -> per-sample LDS)
    float4* wbA = cbuf + (size_t)wid * (RPW * 96);
    float4* wbB = wbA + 96;
    wbA[lane]      = a0;
    wbA[lane + 32] = a1;
    wbA[lane + 64] = a2;
    wbB[lane]      = b0;
    wbB[lane + 32] = b1;
    wbB[lane + 64] = b2;

    const float s   = s_ptr[0];
    const float bgr = bg_color[0];
    const float bgg = bg_color[1];
    const float bgb = bg_color[2];

    __syncwarp();

    process_ray(ray0, lane, sdA, zA, wbA, s, bgr, bgg, bgb, out);
    process_ray(ray1, lane, sdB, zB, wbB, s, bgr, bgg, bgb, out);
}

extern "C" void kernel_launch(void* const* d_in, const int* in_sizes, int n_in,
                              void* d_out, int out_size)
{
    const float* sdf      = (const float*)d_in[0];
    const float* color    = (const float*)d_in[1];
    const float* z_vals   = (const float*)d_in[2];
    const float* s        = (const float*)d_in[3];
    const float* bg_color = (const float*)d_in[4];
    float* out = (float*)d_out;

    neus_render_kernel<<<N_RAYS / (WARPS_PER_BLOCK * RPW), 256>>>(
        sdf, color, z_vals, s, bg_color, out);
}

// round 13
// speedup vs baseline: 1.0234x; 1.0234x over previous
#include <cuda_runtime.h>

// NeuS volume-rendering weights, telescoped closed form. 1 ray per warp
// (R7 structure — best measured), with __launch_bounds__(256,8) forcing
// <=32 regs so 8 blocks/SM fit (occupancy-driven DRAM saturation).
//
//   sig = sigmoid(sdf * s)
//   trans[i] = sig[i]/sig[0]  (telescoping cumprod), trans[0] := 0
//   weight[i] = max(0, sig[i]-sig[i+1]) / sig[0],  1 <= i <= S-2
//   weight[0] = weight[S-1] = 0
//   pixel = sum w*(c - bg) + bg   (background folded; no wsum reduction)
//
// Outputs concatenated into d_out:
//   pixel [R,3] @0, invdepth [R] @R*3, weight [R,S] @R*4

#define N_RAYS    65536
#define N_SAMPLES 128
#define WARPS_PER_BLOCK 8

__global__ void __launch_bounds__(256, 8)
neus_render_kernel(const float* __restrict__ sdf,
                   const float* __restrict__ color,
                   const float* __restrict__ z_vals,
                   const float* __restrict__ s_ptr,
                   const float* __restrict__ bg_color,
                   float* __restrict__ out)
{
    // per-warp color staging: 96 float4 = one ray's [128,3] row (12 KB/block)
    __shared__ float4 cbuf[WARPS_PER_BLOCK * 96];

    const unsigned ray  = (blockIdx.x * blockDim.x + threadIdx.x) >> 5;
    const unsigned lane = threadIdx.x & 31u;
    const unsigned wid  = threadIdx.x >> 5;

    // ---- front-batch all 5 global loads (color coalesced: 4 lines/LDG) ----
    const float4* cg = reinterpret_cast<const float4*>(
                           color + (size_t)ray * N_SAMPLES * 3);
    const float4 t0 = cg[lane];
    const float4 t1 = cg[lane + 32];
    const float4 t2 = cg[lane + 64];
    const float4 sd = reinterpret_cast<const float4*>(
                          sdf + (size_t)ray * N_SAMPLES)[lane];
    const float4 z  = reinterpret_cast<const float4*>(
                          z_vals + (size_t)ray * N_SAMPLES)[lane];

    // stage color through smem: coalesced GMEM layout -> per-sample LDS layout
    float4* wb = cbuf + wid * 96;
    wb[lane]      = t0;
    wb[lane + 32] = t1;
    wb[lane + 64] = t2;

    const float s   = s_ptr[0];
    const float bgr = bg_color[0];
    const float bgg = bg_color[1];
    const float bgb = bg_color[2];

    // sigmoid via MUFU exp + fast division
    const float sg0 = __fdividef(1.0f, 1.0f + __expf(-sd.x * s));
    const float sg1 = __fdividef(1.0f, 1.0f + __expf(-sd.y * s));
    const float sg2 = __fdividef(1.0f, 1.0f + __expf(-sd.z * s));
    const float sg3 = __fdividef(1.0f, 1.0f + __expf(-sd.w * s));

    const float nxt  = __shfl_down_sync(0xffffffffu, sg0, 1);
    const float sig0 = __shfl_sync(0xffffffffu, sg0, 0);
    const float inv0 = __fdividef(1.0f, sig0);

    float w0 = fmaxf(sg0 - sg1, 0.0f) * inv0;
    float w1 = fmaxf(sg1 - sg2, 0.0f) * inv0;
    float w2 = fmaxf(sg2 - sg3, 0.0f) * inv0;
    float w3 = (lane == 31u) ? 0.0f : fmaxf(sg3 - nxt, 0.0f) * inv0;
    if (lane == 0u) w0 = 0.0f;   // trans[0] = 0

    // ---- streaming store of weights [R,S] ----
    float* out_weight = out + (size_t)N_RAYS * 4;
    __stcs(reinterpret_cast<float4*>(out_weight + (size_t)ray * N_SAMPLES) + lane,
           make_float4(w0, w1, w2, w3));

    // ---- invdepth ----
    float invd = w0 * __fdividef(1.0f, z.x)
               + w1 * __fdividef(1.0f, z.y)
               + w2 * __fdividef(1.0f, z.z)
               + w3 * __fdividef(1.0f, z.w);

    // ---- read back this lane's 4 samples of color (conflict-free LDS.128) ----
    __syncwarp();
    const float4 c0 = wb[lane * 3 + 0];
    const float4 c1 = wb[lane * 3 + 1];
    const float4 c2 = wb[lane * 3 + 2];

    // accumulate w*(c - bg); bg added back once on lane 0
    float r = w0 * (c0.x - bgr) + w1 * (c0.w - bgr)
            + w2 * (c1.z - bgr) + w3 * (c2.y - bgr);
    float g = w0 * (c0.y - bgg) + w1 * (c1.x - bgg)
            + w2 * (c1.w - bgg) + w3 * (c2.z - bgg);
    float b = w0 * (c0.z - bgb) + w1 * (c1.y - bgb)
            + w2 * (c2.x - bgb) + w3 * (c2.w - bgb);

    // ---- warp butterfly reduction of 4 values ----
    #pragma unroll
    for (int off = 16; off > 0; off >>= 1) {
        r    += __shfl_xor_sync(0xffffffffu, r,    off);
        g    += __shfl_xor_sync(0xffffffffu, g,    off);
        b    += __shfl_xor_sync(0xffffffffu, b,    off);
        invd += __shfl_xor_sync(0xffffffffu, invd, off);
    }

    if (lane == 0u) {
        out[ray * 3 + 0] = r + bgr;
        out[ray * 3 + 1] = g + bgg;
        out[ray * 3 + 2] = b + bgb;
        out[(size_t)N_RAYS * 3 + ray] = invd;
    }
}

extern "C" void kernel_launch(void* const* d_in, const int* in_sizes, int n_in,
                              void* d_out, int out_size)
{
    const float* sdf      = (const float*)d_in[0];
    const float* color    = (const float*)d_in[1];
    const float* z_vals   = (const float*)d_in[2];
    const float* s        = (const float*)d_in[3];
    const float* bg_color = (const float*)d_in[4];
    float* out = (float*)d_out;

    neus_render_kernel<<<N_RAYS / WARPS_PER_BLOCK, 256>>>(
        sdf, color, z_vals, s, bg_color, out);
}

// round 15
// speedup vs baseline: 1.0441x; 1.0202x over previous
#include <cuda_runtime.h>

// NeuS volume-rendering weights, telescoped closed form. 1 ray per warp,
// 32-reg / 8-blocks-per-SM build. Converged structure: kernel runs at the
// mixed read/write HBM stream ceiling (~6.2 TB/s on this part).
//
//   sig = sigmoid(sdf * s)
//   trans[i] = sig[i]/sig[0]  (telescoping cumprod), trans[0] := 0
//   weight[i] = max(0, sig[i]-sig[i+1]) / sig[0],  1 <= i <= S-2
//   weight[0] = weight[S-1] = 0
//   pixel = sum w*(c - bg) + bg   (background folded; no wsum reduction)
//   invdepth pairs combined: w0/z0 + w1/z1 = (w0*z1 + w1*z0) * rcp(z0*z1)
//
// Outputs concatenated into d_out:
//   pixel [R,3] @0, invdepth [R] @R*3, weight [R,S] @R*4

#define N_RAYS    65536
#define N_SAMPLES 128
#define WARPS_PER_BLOCK 8

__global__ void __launch_bounds__(256, 8)
neus_render_kernel(const float* __restrict__ sdf,
                   const float* __restrict__ color,
                   const float* __restrict__ z_vals,
                   const float* __restrict__ s_ptr,
                   const float* __restrict__ bg_color,
                   float* __restrict__ out)
{
    // per-warp color staging: 96 float4 = one ray's [128,3] row (12 KB/block)
    __shared__ float4 cbuf[WARPS_PER_BLOCK * 96];

    const unsigned ray  = (blockIdx.x * blockDim.x + threadIdx.x) >> 5;
    const unsigned lane = threadIdx.x & 31u;
    const unsigned wid  = threadIdx.x >> 5;

    // ---- front-batch all 5 global loads (color coalesced: 4 lines/LDG) ----
    const float4* cg = reinterpret_cast<const float4*>(
                           color + (size_t)ray * N_SAMPLES * 3);
    const float4 t0 = cg[lane];
    const float4 t1 = cg[lane + 32];
    const float4 t2 = cg[lane + 64];
    const float4 sd = reinterpret_cast<const float4*>(
                          sdf + (size_t)ray * N_SAMPLES)[lane];
    const float4 z  = reinterpret_cast<const float4*>(
                          z_vals + (size_t)ray * N_SAMPLES)[lane];

    // stage color through smem: coalesced GMEM layout -> per-sample LDS layout
    float4* wb = cbuf + wid * 96;
    wb[lane]      = t0;
    wb[lane + 32] = t1;
    wb[lane + 64] = t2;

    const float s   = s_ptr[0];
    const float bgr = bg_color[0];
    const float bgg = bg_color[1];
    const float bgb = bg_color[2];

    // sigmoid via MUFU exp + fast division
    const float sg0 = __fdividef(1.0f, 1.0f + __expf(-sd.x * s));
    const float sg1 = __fdividef(1.0f, 1.0f + __expf(-sd.y * s));
    const float sg2 = __fdividef(1.0f, 1.0f + __expf(-sd.z * s));
    const float sg3 = __fdividef(1.0f, 1.0f + __expf(-sd.w * s));

    const float nxt  = __shfl_down_sync(0xffffffffu, sg0, 1);
    const float sig0 = __shfl_sync(0xffffffffu, sg0, 0);
    const float inv0 = __fdividef(1.0f, sig0);

    float w0 = fmaxf(sg0 - sg1, 0.0f) * inv0;
    float w1 = fmaxf(sg1 - sg2, 0.0f) * inv0;
    float w2 = fmaxf(sg2 - sg3, 0.0f) * inv0;
    float w3 = (lane == 31u) ? 0.0f : fmaxf(sg3 - nxt, 0.0f) * inv0;
    if (lane == 0u) w0 = 0.0f;   // trans[0] = 0

    // ---- streaming store of weights [R,S] ----
    float* out_weight = out + (size_t)N_RAYS * 4;
    __stcs(reinterpret_cast<float4*>(out_weight + (size_t)ray * N_SAMPLES) + lane,
           make_float4(w0, w1, w2, w3));

    // ---- invdepth: pairwise-combined reciprocals (2 RCP instead of 4) ----
    float invd = (w0 * z.y + w1 * z.x) * __fdividef(1.0f, z.x * z.y)
               + (w2 * z.w + w3 * z.z) * __fdividef(1.0f, z.z * z.w);

    // ---- read back this lane's 4 samples of color (conflict-free LDS.128) ----
    __syncwarp();
    const float4 c0 = wb[lane * 3 + 0];
    const float4 c1 = wb[lane * 3 + 1];
    const float4 c2 = wb[lane * 3 + 2];

    // accumulate w*(c - bg); bg added back once at the end
    float r = w0 * (c0.x - bgr) + w1 * (c0.w - bgr)
            + w2 * (c1.z - bgr) + w3 * (c2.y - bgr);
    float g = w0 * (c0.y - bgg) + w1 * (c1.x - bgg)
            + w2 * (c1.w - bgg) + w3 * (c2.z - bgg);
    float b = w0 * (c0.z - bgb) + w1 * (c1.y - bgb)
            + w2 * (c2.x - bgb) + w3 * (c2.w - bgb);

    // ---- warp butterfly reduction of 4 values (result replicated in all lanes) ----
    #pragma unroll
    for (int off = 16; off > 0; off >>= 1) {
        r    += __shfl_xor_sync(0xffffffffu, r,    off);
        g    += __shfl_xor_sync(0xffffffffu, g,    off);
        b    += __shfl_xor_sync(0xffffffffu, b,    off);
        invd += __shfl_xor_sync(0xffffffffu, invd, off);
    }

    // distribute the 4 scalar stores across lanes 0-3 (one STG each)
    if (lane < 3u) {
        const float bg3 = (lane == 0u) ? bgr : (lane == 1u) ? bgg : bgb;
        const float v3  = (lane == 0u) ? r   : (lane == 1u) ? g   : b;
        out[ray * 3 + lane] = v3 + bg3;
    } else if (lane == 3u) {
        out[(size_t)N_RAYS * 3 + ray] = invd;
    }
}

extern "C" void kernel_launch(void* const* d_in, const int* in_sizes, int n_in,
                              void* d_out, int out_size)
{
    const float* sdf      = (const float*)d_in[0];
    const float* color    = (const float*)d_in[1];
    const float* z_vals   = (const float*)d_in[2];
    const float* s        = (const float*)d_in[3];
    const float* bg_color = (const float*)d_in[4];
    float* out = (float*)d_out;

    neus_render_kernel<<<N_RAYS / WARPS_PER_BLOCK, 256>>>(
        sdf, color, z_vals, s, bg_color, out);
}

// round 17
// speedup vs baseline: 1.0508x; 1.0065x over previous
#include <cuda_runtime.h>

// NeuS volume-rendering weights, telescoped closed form. 1 ray per warp,
// 32-reg / 8-blocks-per-SM build. CONVERGED: runs at the mixed read/write
// HBM stream ceiling (193 MB compulsory traffic @ ~6.24 TB/s achieved).
//
//   sig = sigmoid(sdf * s)
//   trans[i] = sig[i]/sig[0]  (telescoping cumprod), trans[0] := 0
//   weight[i] = max(0, sig[i]-sig[i+1]) / sig[0],  1 <= i <= S-2
//   weight[0] = weight[S-1] = 0
//   pixel = sum w*(c - bg) + bg   (background folded; no wsum reduction)
//   invdepth pairs combined: w0/z0 + w1/z1 = (w0*z1 + w1*z0) * rcp(z0*z1)
//
// Outputs concatenated into d_out:
//   pixel [R,3] @0, invdepth [R] @R*3, weight [R,S] @R*4

#define N_RAYS    65536
#define N_SAMPLES 128
#define WARPS_PER_BLOCK 8

__global__ void __launch_bounds__(256, 8)
neus_render_kernel(const float* __restrict__ sdf,
                   const float* __restrict__ color,
                   const float* __restrict__ z_vals,
                   const float* __restrict__ s_ptr,
                   const float* __restrict__ bg_color,
                   float* __restrict__ out)
{
    // per-warp color staging: 96 float4 = one ray's [128,3] row (12 KB/block)
    __shared__ float4 cbuf[WARPS_PER_BLOCK * 96];

    const unsigned ray  = (blockIdx.x * blockDim.x + threadIdx.x) >> 5;
    const unsigned lane = threadIdx.x & 31u;
    const unsigned wid  = threadIdx.x >> 5;

    // uniform scalars first (read-only path, never behind MUFU latency)
    const float s   = __ldg(s_ptr);
    const float bgr = __ldg(bg_color + 0);
    const float bgg = __ldg(bg_color + 1);
    const float bgb = __ldg(bg_color + 2);

    // ---- front-batch all 5 vector loads (color coalesced: 4 lines/LDG) ----
    const float4* cg = reinterpret_cast<const float4*>(
                           color + (size_t)ray * N_SAMPLES * 3);
    const float4 t0 = cg[lane];
    const float4 t1 = cg[lane + 32];
    const float4 t2 = cg[lane + 64];
    const float4 sd = reinterpret_cast<const float4*>(
                          sdf + (size_t)ray * N_SAMPLES)[lane];
    const float4 z  = reinterpret_cast<const float4*>(
                          z_vals + (size_t)ray * N_SAMPLES)[lane];

    // stage color through smem: coalesced GMEM layout -> per-sample LDS layout
    float4* wb = cbuf + wid * 96;
    wb[lane]      = t0;
    wb[lane + 32] = t1;
    wb[lane + 64] = t2;

    // sigmoid via MUFU exp + fast reciprocal
    const float sg0 = __fdividef(1.0f, 1.0f + __expf(-sd.x * s));
    const float sg1 = __fdividef(1.0f, 1.0f + __expf(-sd.y * s));
    const float sg2 = __fdividef(1.0f, 1.0f + __expf(-sd.z * s));
    const float sg3 = __fdividef(1.0f, 1.0f + __expf(-sd.w * s));

    const float nxt  = __shfl_down_sync(0xffffffffu, sg0, 1);
    const float sig0 = __shfl_sync(0xffffffffu, sg0, 0);
    const float inv0 = __fdividef(1.0f, sig0);

    float w0 = fmaxf(sg0 - sg1, 0.0f) * inv0;
    float w1 = fmaxf(sg1 - sg2, 0.0f) * inv0;
    float w2 = fmaxf(sg2 - sg3, 0.0f) * inv0;
    float w3 = (lane == 31u) ? 0.0f : fmaxf(sg3 - nxt, 0.0f) * inv0;
    if (lane == 0u) w0 = 0.0f;   // trans[0] = 0

    // ---- streaming store of weights [R,S] ----
    float* out_weight = out + (size_t)N_RAYS * 4;
    __stcs(reinterpret_cast<float4*>(out_weight + (size_t)ray * N_SAMPLES) + lane,
           make_float4(w0, w1, w2, w3));

    // ---- invdepth: pairwise-combined reciprocals (2 RCP instead of 4) ----
    float invd = (w0 * z.y + w1 * z.x) * __fdividef(1.0f, z.x * z.y)
               + (w2 * z.w + w3 * z.z) * __fdividef(1.0f, z.z * z.w);

    // ---- read back this lane's 4 samples of color (conflict-free LDS.128) ----
    __syncwarp();
    const float4 c0 = wb[lane * 3 + 0];
    const float4 c1 = wb[lane * 3 + 1];
    const float4 c2 = wb[lane * 3 + 2];

    // accumulate w*(c - bg); bg added back once at the end
    float r = w0 * (c0.x - bgr) + w1 * (c0.w - bgr)
            + w2 * (c1.z - bgr) + w3 * (c2.y - bgr);
    float g = w0 * (c0.y - bgg) + w1 * (c1.x - bgg)
            + w2 * (c1.w - bgg) + w3 * (c2.z - bgg);
    float b = w0 * (c0.z - bgb) + w1 * (c1.y - bgb)
            + w2 * (c2.x - bgb) + w3 * (c2.w - bgb);

    // ---- warp butterfly reduction of 4 values (result replicated in all lanes) ----
    #pragma unroll
    for (int off = 16; off > 0; off >>= 1) {
        r    += __shfl_xor_sync(0xffffffffu, r,    off);
        g    += __shfl_xor_sync(0xffffffffu, g,    off);
        b    += __shfl_xor_sync(0xffffffffu, b,    off);
        invd += __shfl_xor_sync(0xffffffffu, invd, off);
    }

    // distribute the 4 scalar stores across lanes 0-3 (one STG each)
    if (lane < 3u) {
        const float bg3 = (lane == 0u) ? bgr : (lane == 1u) ? bgg : bgb;
        const float v3  = (lane == 0u) ? r   : (lane == 1u) ? g   : b;
        out[ray * 3 + lane] = v3 + bg3;
    } else if (lane == 3u) {
        out[(size_t)N_RAYS * 3 + ray] = invd;
    }
}

extern "C" void kernel_launch(void* const* d_in, const int* in_sizes, int n_in,
                              void* d_out, int out_size)
{
    const float* sdf      = (const float*)d_in[0];
    const float* color    = (const float*)d_in[1];
    const float* z_vals   = (const float*)d_in[2];
    const float* s        = (const float*)d_in[3];
    const float* bg_color = (const float*)d_in[4];
    float* out = (float*)d_out;

    neus_render_kernel<<<N_RAYS / WARPS_PER_BLOCK, 256>>>(
        sdf, color, z_vals, s, bg_color, out);
}